// round 16
// baseline (speedup 1.0000x reference)
#include <cuda_runtime.h>
#include <math.h>

// ---------------------------------------------------------------------------
// SindyLayer: replicate jax.experimental.ode.odeint (dopri5, rtol=atol=1e-3)
// for dy/dt = iAy split into (u,v): du/dt = -A v, dv/dt = A u, A sym 64x64.
// Output: u (real part) at t = 1..128, shape [4096, 128, 64] f32.
//
// ROUND-16 (base = round 13, NTH=256, best 1941.8us): stage states live in
// per-lane registers; rhs obtains y[r][4kp..4kp+3] via two 64-bit
// __shfl_sync from the owning lanes (2kp, 2kp+1) instead of SMEM broadcast
// loads. Removes the dominant crossbar traffic (y broadcasts + yalt stores)
// and all per-stage syncs (k slots are thread-own, A is read-only).
// Shuffles move exact bits; FFMA2 chains/kp order unchanged -> k values and
// trajectory bitwise identical to round 13. A cached in regs for kp 0..5.
// Controller: per-slot release/acquire global reduction, split publish/gather
// with speculative interp (double-buffered P), replay-deterministic.
// ---------------------------------------------------------------------------

#define HID      64
#define RPB      32
#define NTH      256
#define NBLK     128
#define FORECAST 128
#define ARR      2048            // floats per (u or v) array per block
#define YSZ      4096            // u+v
#define NKREG    6               // kp slots of A cached in registers

// smem layout (floats)
#define OFF_A 0                        // AE: 2048 floats, AO: 2048 floats
#define OFF_Y 4096                     // two y buffers (init only)
#define OFF_K (OFF_Y + 2*YSZ)          // 5 k slots: k1..k5
#define OFF_P (OFF_K + 5*YSZ)          // interp: 2 parity x 5 arrays (u only)
#define PH    (5*ARR)
#define OFF_R (OFF_P + 2*PH)           // reduction scratch
#define SM_FLOATS (OFF_R + 8 + 2*NBLK + 8)
#define SMEM_BYTES (SM_FLOATS*4)       // ~214 KB

typedef unsigned long long u64;

// ---- global controller state (persistent; g_seq reset each launch) ----
__device__ float    g_val[2][2*NBLK];  // double-buffered payload (2 channels)
__device__ unsigned g_seq[NBLK];       // per-block monotonically increasing round id

// Dopri5 tableau exactly as in jax/experimental/ode.py
__device__ constexpr float BETAc[6][6] = {
  {(float)(1.0/5.0), 0.f, 0.f, 0.f, 0.f, 0.f},
  {(float)(3.0/40.0), (float)(9.0/40.0), 0.f, 0.f, 0.f, 0.f},
  {(float)(44.0/45.0), (float)(-56.0/15.0), (float)(32.0/9.0), 0.f, 0.f, 0.f},
  {(float)(19372.0/6561.0), (float)(-25360.0/2187.0), (float)(64448.0/6561.0),
   (float)(-212.0/729.0), 0.f, 0.f},
  {(float)(9017.0/3168.0), (float)(-355.0/33.0), (float)(46732.0/5247.0),
   (float)(49.0/176.0), (float)(-5103.0/18656.0), 0.f},
  {(float)(35.0/384.0), 0.f, (float)(500.0/1113.0), (float)(125.0/192.0),
   (float)(-2187.0/6784.0), (float)(11.0/84.0)}
};

// ---- packed f32x2 helpers (FFMA2 path for rhs) ----
__device__ __forceinline__ void ffma2(u64& d, u64 a, u64 b) {
  asm("fma.rn.f32x2 %0, %1, %2, %0;" : "+l"(d) : "l"(a), "l"(b));
}
__device__ __forceinline__ u64 pack2(float x, float y) {
  u64 r; unsigned xi = __float_as_uint(x), yi = __float_as_uint(y);
  asm("mov.b64 %0, {%1, %2};" : "=l"(r) : "r"(xi), "r"(yi));
  return r;
}
__device__ __forceinline__ float2 unpack2(u64 v) {
  unsigned lo, hi;
  asm("mov.b64 {%0, %1}, %2;" : "=r"(lo), "=r"(hi) : "l"(v));
  return make_float2(__uint_as_float(lo), __uint_as_float(hi));
}

// Deterministic block-wide sum; result uniform across all 256 threads.
__device__ __forceinline__ float block_sum(float v, float* red) {
  __syncthreads();
  #pragma unroll
  for (int o = 16; o; o >>= 1) v += __shfl_down_sync(0xffffffffu, v, o);
  if ((threadIdx.x & 31) == 0) red[threadIdx.x >> 5] = v;
  __syncthreads();
  float s = red[0];
  #pragma unroll
  for (int w = 1; w < NTH/32; w++) s += red[w];
  return s;
}

__device__ __forceinline__ unsigned ld_seq_cg(const unsigned* p) {
  unsigned v;
  asm volatile("ld.global.cg.u32 %0, [%1];" : "=r"(v) : "l"(p));
  return v;
}

// Release: payload __stcg -> __threadfence -> atomicExch(seq, rno).
__device__ __forceinline__ void gs_publish(float v, float* red, unsigned rno) {
  const int par = rno & 1;
  float b0 = block_sum(v, red);
  if (threadIdx.x == 0) {
    __stcg(&g_val[par][blockIdx.x], b0);
    __threadfence();
    atomicExch(&g_seq[blockIdx.x], rno);
  }
}
// Acquire: per-slot spin, fence, pull to SMEM, fixed-order sum (bitwise-uniform).
__device__ __forceinline__ float gs_gather(float* red, unsigned rno) {
  const int par = rno & 1;
  float* red2 = red + 8;
  const int b = threadIdx.x;
  if (b < NBLK) {
    while (ld_seq_cg(&g_seq[b]) < rno) __nanosleep(32);
    __threadfence();
    red2[b] = __ldcg(&g_val[par][b]);
  }
  __syncthreads();
  float a0 = 0.f;
  for (int i = 0; i < NBLK; i++) a0 += red2[i];
  return a0;
}

// Two-channel variant for init (publish+gather fused; doubles as grid barrier).
__device__ __forceinline__ void global_sum2(float v0, float v1, bool two,
                                            float* red, unsigned rno,
                                            float& s0, float& s1) {
  const int par = rno & 1;
  float b0 = block_sum(v0, red);
  float b1 = two ? block_sum(v1, red) : 0.f;
  float* red2 = red + 8;
  if (threadIdx.x == 0) {
    __stcg(&g_val[par][blockIdx.x], b0);
    if (two) __stcg(&g_val[par][NBLK + blockIdx.x], b1);
    __threadfence();
    atomicExch(&g_seq[blockIdx.x], rno);
  }
  const int b = threadIdx.x;
  if (b < NBLK) {
    while (ld_seq_cg(&g_seq[b]) < rno) __nanosleep(32);
    __threadfence();
    red2[b] = __ldcg(&g_val[par][b]);
    if (two) red2[NBLK + b] = __ldcg(&g_val[par][NBLK + b]);
  }
  __syncthreads();
  float a0 = 0.f, a1 = 0.f;
  for (int i = 0; i < NBLK; i++) {
    a0 += red2[i];
    if (two) a1 += red2[NBLK + i];
  }
  s0 = a0; s1 = a1;
}

// RHS: k_u = -(v @ A^T), k_v = (u @ A^T). Thread owns 4 rows x 2 cols.
// Stage state comes from per-lane registers via shuffles: lane L owns cols
// 2L,2L+1; y[r][4kp..4kp+3] = (shfl lane 2kp, shfl lane 2kp+1), exact bits.
// kp 0..NKREG-1: A from registers; else parity-split SMEM (conflict-free).
// Per-(row,col) even/odd-k FFMA2 order identical to rounds 3-13.
template<bool TOREG, bool TOSM>
__device__ __forceinline__ void rhs_eval(const u64 (&yiU)[4], const u64 (&yiV)[4],
                                         float* __restrict__ kd,
                                         const float* __restrict__ Apk,
                                         const ulonglong2 (&ArE)[NKREG],
                                         const ulonglong2 (&ArO)[NKREG],
                                         int c0, int r0, int j,
                                         float (&oU)[4][2], float (&oV)[4][2])
{
  const ulonglong2* __restrict__ AE2 = (const ulonglong2*)Apk;
  const ulonglong2* __restrict__ AO2 = (const ulonglong2*)(Apk + ARR);
  u64 aU[4][2], aV[4][2];
  #pragma unroll
  for (int r = 0; r < 4; r++) {
    aU[r][0] = 0ull; aU[r][1] = 0ull;
    aV[r][0] = 0ull; aV[r][1] = 0ull;
  }
  #pragma unroll
  for (int kp = 0; kp < 16; kp++) {
    ulonglong2 A0, A1;
    if (kp < NKREG) { A0 = ArE[kp]; A1 = ArO[kp]; }
    else            { A0 = AE2[kp*32 + j]; A1 = AO2[kp*32 + j]; }
    #pragma unroll
    for (int r = 0; r < 4; r++) {
      u64 vlo = __shfl_sync(0xffffffffu, yiV[r], 2*kp);
      u64 vhi = __shfl_sync(0xffffffffu, yiV[r], 2*kp + 1);
      u64 ulo = __shfl_sync(0xffffffffu, yiU[r], 2*kp);
      u64 uhi = __shfl_sync(0xffffffffu, yiU[r], 2*kp + 1);
      ffma2(aU[r][0], A0.x, vlo); ffma2(aU[r][0], A0.y, vhi);
      ffma2(aV[r][0], A0.x, ulo); ffma2(aV[r][0], A0.y, uhi);
      ffma2(aU[r][1], A1.x, vlo); ffma2(aU[r][1], A1.y, vhi);
      ffma2(aV[r][1], A1.x, ulo); ffma2(aV[r][1], A1.y, uhi);
    }
  }
  #pragma unroll
  for (int r = 0; r < 4; r++) {
    float2 su0 = unpack2(aU[r][0]), su1 = unpack2(aU[r][1]);
    float2 sv0 = unpack2(aV[r][0]), sv1 = unpack2(aV[r][1]);
    float2 ku = make_float2(-(su0.x + su0.y), -(su1.x + su1.y));
    float2 kv = make_float2( (sv0.x + sv0.y),  (sv1.x + sv1.y));
    if (TOSM) {
      *(float2*)(kd + (r0+r)*HID + c0)       = ku;
      *(float2*)(kd + ARR + (r0+r)*HID + c0) = kv;
    }
    if (TOREG) {
      oU[r][0] = ku.x; oU[r][1] = ku.y;
      oV[r][0] = kv.x; oV[r][1] = kv.y;
    }
  }
}

__global__ void reset_kernel() {
  if (threadIdx.x < NBLK) g_seq[threadIdx.x] = 0u;
}

// Stage-state build helpers: identical per-element fmaf chains as rds 10-13;
// result goes to per-lane yi registers (packed) instead of SMEM.
#define AXBEGIN float2 au = make_float2(0.f,0.f), av = make_float2(0.f,0.f);
#define AXREG(B, KU, KV) { const float b_ = (B); \
  au.x = fmaf(b_, KU[r][0], au.x); au.y = fmaf(b_, KU[r][1], au.y); \
  av.x = fmaf(b_, KV[r][0], av.x); av.y = fmaf(b_, KV[r][1], av.y); }
#define AXSM(B, BASE) { const float b_ = (B); \
  float2 tu_ = *(const float2*)((BASE) + (r0+r)*HID + c0); \
  float2 tv_ = *(const float2*)((BASE) + ARR + (r0+r)*HID + c0); \
  au.x = fmaf(b_, tu_.x, au.x); au.y = fmaf(b_, tu_.y, au.y); \
  av.x = fmaf(b_, tv_.x, av.x); av.y = fmaf(b_, tv_.y, av.y); }
#define AXEND { \
  yiU[r] = pack2(fmaf(dt, au.x, yUr[r][0]), fmaf(dt, au.y, yUr[r][1])); \
  yiV[r] = pack2(fmaf(dt, av.x, yVr[r][0]), fmaf(dt, av.y, yVr[r][1])); }

__global__ void __launch_bounds__(NTH, 1)
sindy_kernel(const float* __restrict__ x,
             const float* __restrict__ tri,
             float* __restrict__ out)
{
  extern __shared__ float sm[];
  const int tid  = threadIdx.x;
  const int c0   = (tid & 31) * 2;      // 2 adjacent columns
  const int r0   = (tid >> 5) * 4;      // warp owns 4 rows
  const int j    = tid & 31;            // lane
  const int brow = blockIdx.x * RPB;

  float* Apk = sm + OFF_A;
  float* K   = sm + OFF_K;
  float* KS1 = K;
  float* KS2 = K + 1*YSZ;
  float* KS3 = K + 2*YSZ;
  float* KS4 = K + 3*YSZ;
  float* KS5 = K + 4*YSZ;
  float* Pb0 = sm + OFF_P;
  float* RED = sm + OFF_R;

  unsigned rno = 1;     // reduction round id (uniform across grid)
  int pp = 0;           // P parity (valid interp coefficients)

  // per-thread element registers (rows r0..r0+3, cols c0,c0+1)
  float yUr[4][2], yVr[4][2];
  float kU0[4][2], kV0[4][2];
  float kU6[4][2], kV6[4][2];
  u64   yiU[4], yiV[4];                 // current stage state (packed)
  ulonglong2 ArE[NKREG], ArO[NKREG];    // A cache, kp 0..NKREG-1

  const float CE0 = (float)(35.0/384.0 - 1951.0/21600.0);
  const float CE2 = (float)(500.0/1113.0 - 22642.0/50085.0);
  const float CE3 = (float)(125.0/192.0 - 451.0/720.0);
  const float CE4 = (float)(-2187.0/6784.0 + 12231.0/42400.0);
  const float CE5 = (float)(11.0/84.0 - 649.0/6300.0);
  const float CE6 = (float)(-1.0/60.0);
  const float CM0 = (float)(6025192743.0/30085553152.0/2.0);
  const float CM2 = (float)(51252292925.0/65400821598.0/2.0);
  const float CM3 = (float)(-2691868925.0/45128329728.0/2.0);
  const float CM4 = (float)(187940372067.0/1594534317056.0/2.0);
  const float CM5 = (float)(-1776094331.0/19743644256.0/2.0);
  const float CM6 = (float)(11237099.0/235043384.0/2.0);

  // Build parity-split kp-major A:
  //  AE[kp*128 + jj*4 + m] = A[2jj  ][kp*4+m]
  //  AO[kp*128 + jj*4 + m] = A[2jj+1][kp*4+m]
  for (int idx = tid; idx < HID*HID; idx += NTH) {
    int half = idx >> 11;
    int rem  = idx & 2047;
    int kp   = rem >> 7;
    int w    = rem & 127;
    int jj   = w >> 2, m = w & 3;
    int cc   = 2*jj + half;
    int k    = kp*4 + m;
    int R = cc > k ? cc : k, C = cc > k ? k : cc;
    Apk[half*ARR + kp*128 + jj*4 + m] = tri[R*(R+1)/2 + C];
  }

  // y0 = (x, 0); emit output slice t=1 (== y0 per odeint semantics)
  {
    float* Y0 = sm + OFF_Y;
    #pragma unroll
    for (int q = 0; q < 2; q++) {
      int e4 = tid + q*256;
      float4 xv = ((const float4*)x)[brow*16 + e4];
      ((float4*)Y0)[e4]         = xv;
      ((float4*)(Y0 + ARR))[e4] = make_float4(0.f, 0.f, 0.f, 0.f);
      int e = e4*4; int r = e >> 6; int h = e & 63;
      *(float4*)(out + ((size_t)(brow + r)*FORECAST + 0)*HID + h) = xv;
    }
  }
  __syncthreads();

  // load A register cache (same bits as SMEM parity arrays)
  {
    const ulonglong2* AE2 = (const ulonglong2*)Apk;
    const ulonglong2* AO2 = (const ulonglong2*)(Apk + ARR);
    #pragma unroll
    for (int kp = 0; kp < NKREG; kp++) {
      ArE[kp] = AE2[kp*32 + j];
      ArO[kp] = AO2[kp*32 + j];
    }
  }

  float* ycur = sm + OFF_Y;
  float* yalt = sm + OFF_Y + YSZ;

  // yi <- y0 (thread-own), then f0 -> k0 regs + SMEM slot KS1 for init norms
  #pragma unroll
  for (int r = 0; r < 4; r++) {
    yiU[r] = *(const u64*)(ycur + (r0+r)*HID + c0);
    yiV[r] = *(const u64*)(ycur + ARR + (r0+r)*HID + c0);
  }
  rhs_eval<true, true>(yiU, yiV, K, Apk, ArE, ArO, c0, r0, j, kU0, kV0);
  __syncthreads();

  // ---- initial_step_size (Hairer, order=4), GLOBAL norms (round-3 exact) ----
  float dt;
  {
    float s0 = 0.f, s1 = 0.f;
    #pragma unroll
    for (int q = 0; q < 4; q++) {
      int e4 = tid + q*256;
      float4 y4 = ((const float4*)ycur)[e4];
      float4 f4 = ((const float4*)K)[e4];
      float ys[4] = {y4.x, y4.y, y4.z, y4.w};
      float fs[4] = {f4.x, f4.y, f4.z, f4.w};
      #pragma unroll
      for (int m = 0; m < 4; m++) {
        float sc = 1e-3f + 1e-3f*fabsf(ys[m]);
        float a0 = ys[m]/sc, a1 = fs[m]/sc;
        s0 = fmaf(a0, a0, s0); s1 = fmaf(a1, a1, s1);
      }
    }
    float t0s, t1s;
    global_sum2(s0, s1, true, RED, rno, t0s, t1s); rno++;
    float d0 = sqrtf(t0s);
    float d1 = sqrtf(t1s);
    float h0 = (d0 < 1e-5f || d1 < 1e-5f) ? 1e-6f : 0.01f*d0/d1;
    #pragma unroll
    for (int q = 0; q < 4; q++) {
      int e4 = tid + q*256;
      float4 y4 = ((const float4*)ycur)[e4];
      float4 f4 = ((const float4*)K)[e4];
      float4 r4;
      r4.x = fmaf(h0, f4.x, y4.x); r4.y = fmaf(h0, f4.y, y4.y);
      r4.z = fmaf(h0, f4.z, y4.z); r4.w = fmaf(h0, f4.w, y4.w);
      ((float4*)yalt)[e4] = r4;
    }
    __syncthreads();
    // probe rhs from yalt (thread-own reload into yi regs)
    #pragma unroll
    for (int r = 0; r < 4; r++) {
      yiU[r] = *(const u64*)(yalt + (r0+r)*HID + c0);
      yiV[r] = *(const u64*)(yalt + ARR + (r0+r)*HID + c0);
    }
    rhs_eval<false, true>(yiU, yiV, K + YSZ, Apk, ArE, ArO, c0, r0, j, kU6, kV6);
    __syncthreads();
    float s2 = 0.f;
    #pragma unroll
    for (int q = 0; q < 4; q++) {
      int e4 = tid + q*256;
      float4 y4  = ((const float4*)ycur)[e4];
      float4 f0v = ((const float4*)K)[e4];
      float4 f1v = ((const float4*)(K + YSZ))[e4];
      float ys[4] = {y4.x, y4.y, y4.z, y4.w};
      float a0[4] = {f0v.x, f0v.y, f0v.z, f0v.w};
      float a1[4] = {f1v.x, f1v.y, f1v.z, f1v.w};
      #pragma unroll
      for (int m = 0; m < 4; m++) {
        float sc = 1e-3f + 1e-3f*fabsf(ys[m]);
        float d = (a1[m] - a0[m])/sc;
        s2 = fmaf(d, d, s2);
      }
    }
    float t2s, dum;
    global_sum2(s2, 0.f, false, RED, rno, t2s, dum); rno++;
    float d2 = sqrtf(t2s) / h0;
    float h1;
    if (d1 <= 1e-15f && d2 <= 1e-15f) h1 = fmaxf(1e-6f, h0*1e-3f);
    else                              h1 = powf(0.01f/fmaxf(d1, d2), 0.2f);
    dt = fminf(100.f*h0, h1);
  }

  // load thread-own y elements into registers
  #pragma unroll
  for (int r = 0; r < 4; r++) {
    float2 yu = *(const float2*)(ycur + (r0+r)*HID + c0);
    float2 yv = *(const float2*)(ycur + ARR + (r0+r)*HID + c0);
    yUr[r][0] = yu.x; yUr[r][1] = yu.y;
    yVr[r][0] = yv.x; yVr[r][1] = yv.y;
  }

  float t = 1.f, last_t = 1.f;

  // ---- main scan over output targets ----
  for (int tgt = 2; tgt <= FORECAST; tgt++) {
    float tf = (float)tgt;
    int guard = 0;
    while (t < tf && dt > 0.f && guard < 100000) {
      guard++;

      // ---- stages 1..6: register-resident yi + shuffle-fed rhs; no syncs
      //      (k slots are produced/consumed thread-own; A is read-only) ----
      // S1 -> k1 (SMEM)
      #pragma unroll
      for (int r = 0; r < 4; r++) { AXBEGIN AXREG(BETAc[0][0], kU0, kV0) AXEND }
      rhs_eval<false, true>(yiU, yiV, KS1, Apk, ArE, ArO, c0, r0, j, kU6, kV6);
      // S2 -> k2
      #pragma unroll
      for (int r = 0; r < 4; r++) { AXBEGIN
        AXREG(BETAc[1][0], kU0, kV0) AXSM(BETAc[1][1], KS1) AXEND }
      rhs_eval<false, true>(yiU, yiV, KS2, Apk, ArE, ArO, c0, r0, j, kU6, kV6);
      // S3 -> k3
      #pragma unroll
      for (int r = 0; r < 4; r++) { AXBEGIN
        AXREG(BETAc[2][0], kU0, kV0) AXSM(BETAc[2][1], KS1)
        AXSM(BETAc[2][2], KS2) AXEND }
      rhs_eval<false, true>(yiU, yiV, KS3, Apk, ArE, ArO, c0, r0, j, kU6, kV6);
      // S4 -> k4
      #pragma unroll
      for (int r = 0; r < 4; r++) { AXBEGIN
        AXREG(BETAc[3][0], kU0, kV0) AXSM(BETAc[3][1], KS1)
        AXSM(BETAc[3][2], KS2) AXSM(BETAc[3][3], KS3) AXEND }
      rhs_eval<false, true>(yiU, yiV, KS4, Apk, ArE, ArO, c0, r0, j, kU6, kV6);
      // S5 -> k5
      #pragma unroll
      for (int r = 0; r < 4; r++) { AXBEGIN
        AXREG(BETAc[4][0], kU0, kV0) AXSM(BETAc[4][1], KS1)
        AXSM(BETAc[4][2], KS2) AXSM(BETAc[4][3], KS3)
        AXSM(BETAc[4][4], KS4) AXEND }
      rhs_eval<false, true>(yiU, yiV, KS5, Apk, ArE, ArO, c0, r0, j, kU6, kV6);
      // S6 -> yi == y1; k6 -> regs (beta[5][1] == 0 -> k1 term skipped)
      #pragma unroll
      for (int r = 0; r < 4; r++) { AXBEGIN
        AXREG(BETAc[5][0], kU0, kV0)
        AXSM(BETAc[5][2], KS2) AXSM(BETAc[5][3], KS3)
        AXSM(BETAc[5][4], KS4) AXSM(BETAc[5][5], KS5) AXEND }
      rhs_eval<true, false>(yiU, yiV, K, Apk, ArE, ArO, c0, r0, j, kU6, kV6);
      // yiU/yiV hold y1 (FSAL)

      // ---- error-ratio partial (regs + thread-own k SMEM; round-13 order) --
      float ss = 0.f;
      #pragma unroll
      for (int r = 0; r < 4; r++) {
        const int obr = (r0+r)*HID + c0;
        float2 k2u = *(const float2*)(KS2 + obr);
        float2 k2v = *(const float2*)(KS2 + ARR + obr);
        float2 k3u = *(const float2*)(KS3 + obr);
        float2 k3v = *(const float2*)(KS3 + ARR + obr);
        float2 k4u = *(const float2*)(KS4 + obr);
        float2 k4v = *(const float2*)(KS4 + ARR + obr);
        float2 k5u = *(const float2*)(KS5 + obr);
        float2 k5v = *(const float2*)(KS5 + ARR + obr);
        float2 y1u = unpack2(yiU[r]);
        float2 y1v = unpack2(yiV[r]);
        #define EC(K0,K2,K3,K4,K5,K6,Y0,Y1) { \
          float er_ = dt*(CE0*(K0) + CE2*(K2) + CE3*(K3) + CE4*(K4) + CE5*(K5) + CE6*(K6)); \
          float tol_ = 1e-3f + 1e-3f*fmaxf(fabsf(Y0), fabsf(Y1)); \
          float rr_ = er_/tol_; ss = fmaf(rr_, rr_, ss); }
        EC(kU0[r][0],k2u.x,k3u.x,k4u.x,k5u.x,kU6[r][0],yUr[r][0],y1u.x)
        EC(kU0[r][1],k2u.y,k3u.y,k4u.y,k5u.y,kU6[r][1],yUr[r][1],y1u.y)
        EC(kV0[r][0],k2v.x,k3v.x,k4v.x,k5v.x,kV6[r][0],yVr[r][0],y1v.x)
        EC(kV0[r][1],k2v.y,k3v.y,k4v.y,k5v.y,kV6[r][1],yVr[r][1],y1v.y)
        #undef EC
      }
      gs_publish(ss, RED, rno);

      // ---- speculative interp coefficients (u only) into P[pp^1] ----
      {
        float* Pn = Pb0 + (pp^1)*PH;
        #pragma unroll
        for (int r = 0; r < 4; r++) {
          const int obr = (r0+r)*HID + c0;
          float2 k2u = *(const float2*)(KS2 + obr);
          float2 k3u = *(const float2*)(KS3 + obr);
          float2 k4u = *(const float2*)(KS4 + obr);
          float2 k5u = *(const float2*)(KS5 + obr);
          float2 y1u = unpack2(yiU[r]);
          float2 A2f, B2f, C2f, D2f, E2f;
          #define IC(W, K0,K2,K3,K4,K5,K6,Y0,Y1) { \
            float ym = fmaf(dt, CM0*(K0) + CM2*(K2) + CM3*(K3) + CM4*(K4) + CM5*(K5) + CM6*(K6), (Y0)); \
            float D0 = dt*(K0), D1 = dt*(K6); \
            A2f.W = -2.f*D0 + 2.f*D1 -  8.f*(Y0) -  8.f*(Y1) + 16.f*ym; \
            B2f.W =  5.f*D0 - 3.f*D1 + 18.f*(Y0) + 14.f*(Y1) - 32.f*ym; \
            C2f.W = -4.f*D0 +     D1 - 11.f*(Y0) -  5.f*(Y1) + 16.f*ym; \
            D2f.W = D0; E2f.W = (Y0); }
          IC(x, kU0[r][0],k2u.x,k3u.x,k4u.x,k5u.x,kU6[r][0],yUr[r][0],y1u.x)
          IC(y, kU0[r][1],k2u.y,k3u.y,k4u.y,k5u.y,kU6[r][1],yUr[r][1],y1u.y)
          #undef IC
          *(float2*)(Pn + 0*ARR + obr) = A2f;
          *(float2*)(Pn + 1*ARR + obr) = B2f;
          *(float2*)(Pn + 2*ARR + obr) = C2f;
          *(float2*)(Pn + 3*ARR + obr) = D2f;
          *(float2*)(Pn + 4*ARR + obr) = E2f;
        }
      }

      float tss = gs_gather(RED, rno); rno++;
      float ratio  = sqrtf(tss * (1.f/524288.f));
      float er     = fmaxf(ratio, 1e-10f);
      float dfac   = (ratio < 1.f) ? 1.f : 0.2f;
      float factor = fminf(10.f, fmaxf(0.9f*powf(er, -0.2f), dfac));
      bool  accept = (ratio <= 1.f);

      if (accept) {
        pp ^= 1;                         // speculative P becomes valid
        // FSAL: k0 <- k6; y <- y1 (all register moves)
        #pragma unroll
        for (int r = 0; r < 4; r++) {
          kU0[r][0] = kU6[r][0]; kU0[r][1] = kU6[r][1];
          kV0[r][0] = kV6[r][0]; kV0[r][1] = kV6[r][1];
          float2 yu = unpack2(yiU[r]);
          float2 yv = unpack2(yiV[r]);
          yUr[r][0] = yu.x; yUr[r][1] = yu.y;
          yVr[r][0] = yv.x; yVr[r][1] = yv.y;
        }
        last_t = t; t = t + dt;
      }
      // reject: k0/y regs intact; nothing to restore
      dt = dt * factor;
      __syncthreads();   // protect P / k slots before next iteration
    }

    // evaluate interpolation polynomial at the target and store
    float xr = (tf - last_t) / (t - last_t);
    const float* Pc = Pb0 + pp*PH;
    #pragma unroll
    for (int q = 0; q < 2; q++) {
      int e4 = tid + q*256;
      float4 A4 = ((const float4*)Pc)[e4];
      float4 B4 = ((const float4*)(Pc +   ARR))[e4];
      float4 C4 = ((const float4*)(Pc + 2*ARR))[e4];
      float4 D4 = ((const float4*)(Pc + 3*ARR))[e4];
      float4 E4 = ((const float4*)(Pc + 4*ARR))[e4];
      float4 o;
      o.x = fmaf(fmaf(fmaf(fmaf(A4.x, xr, B4.x), xr, C4.x), xr, D4.x), xr, E4.x);
      o.y = fmaf(fmaf(fmaf(fmaf(A4.y, xr, B4.y), xr, C4.y), xr, D4.y), xr, E4.y);
      o.z = fmaf(fmaf(fmaf(fmaf(A4.z, xr, B4.z), xr, C4.z), xr, D4.z), xr, E4.z);
      o.w = fmaf(fmaf(fmaf(fmaf(A4.w, xr, B4.w), xr, C4.w), xr, D4.w), xr, E4.w);
      int e = e4*4; int r = e >> 6; int h = e & 63;
      *(float4*)(out + ((size_t)(brow + r)*FORECAST + (tgt - 1))*HID + h) = o;
    }
  }
}

extern "C" void kernel_launch(void* const* d_in, const int* in_sizes, int n_in,
                              void* d_out, int out_size) {
  (void)in_sizes; (void)n_in; (void)out_size;
  const float* x   = (const float*)d_in[0];
  const float* tri = (const float*)d_in[1];
  float* out = (float*)d_out;
  cudaFuncSetAttribute(sindy_kernel,
                       cudaFuncAttributeMaxDynamicSharedMemorySize, SMEM_BYTES);
  reset_kernel<<<1, 128>>>();
  sindy_kernel<<<NBLK, NTH, SMEM_BYTES>>>(x, tri, out);
}

// round 17
// speedup vs baseline: 1.3267x; 1.3267x over previous
#include <cuda_runtime.h>
#include <math.h>

// ---------------------------------------------------------------------------
// SindyLayer: replicate jax.experimental.ode.odeint (dopri5, rtol=atol=1e-3)
// for dy/dt = iAy split into (u,v): du/dt = -A v, dv/dt = A u, A sym 64x64.
// Output: u (real part) at t = 1..128, shape [4096, 128, 64] f32.
//
// ROUND-17 (base = round 13, best 1941.8us): NKREG 8 -> 10 (A register cache
// covers kp 0..9; bitwise-neutral) and fixed-shape tree reductions in the
// gather/block sums (deterministic; changes ratio ulps only, 3x precedent).
// Everything else byte-identical to round 13: NTH=256, warp owns 4 rows x all
// 64 cols (self-contained -> syncwarp stages), k0/k6 + y register-resident,
// k1..k5 thread-own SMEM slots, parity-split conflict-free A, per-slot
// release/acquire global controller with speculative interp.
// ---------------------------------------------------------------------------

#define HID      64
#define RPB      32
#define NTH      256
#define NBLK     128
#define FORECAST 128
#define ARR      2048            // floats per (u or v) array per block
#define YSZ      4096            // u+v
#define NKREG    10              // kp slots of A cached in registers

// smem layout (floats)
#define OFF_A 0                        // AE: 2048 floats, AO: 2048 floats
#define OFF_Y 4096                     // two parity y buffers [u|v]
#define OFF_K (OFF_Y + 2*YSZ)          // 5 k slots: k1..k5
#define OFF_P (OFF_K + 5*YSZ)          // interp: 2 parity x 5 arrays (u only)
#define PH    (5*ARR)
#define OFF_R (OFF_P + 2*PH)           // reduction scratch
#define SM_FLOATS (OFF_R + 8 + 2*NBLK + 8)
#define SMEM_BYTES (SM_FLOATS*4)       // ~214 KB

typedef unsigned long long u64;

// ---- global controller state (persistent; g_seq reset each launch) ----
__device__ float    g_val[2][2*NBLK];  // double-buffered payload (2 channels)
__device__ unsigned g_seq[NBLK];       // per-block monotonically increasing round id

// Dopri5 tableau exactly as in jax/experimental/ode.py
__device__ constexpr float BETAc[6][6] = {
  {(float)(1.0/5.0), 0.f, 0.f, 0.f, 0.f, 0.f},
  {(float)(3.0/40.0), (float)(9.0/40.0), 0.f, 0.f, 0.f, 0.f},
  {(float)(44.0/45.0), (float)(-56.0/15.0), (float)(32.0/9.0), 0.f, 0.f, 0.f},
  {(float)(19372.0/6561.0), (float)(-25360.0/2187.0), (float)(64448.0/6561.0),
   (float)(-212.0/729.0), 0.f, 0.f},
  {(float)(9017.0/3168.0), (float)(-355.0/33.0), (float)(46732.0/5247.0),
   (float)(49.0/176.0), (float)(-5103.0/18656.0), 0.f},
  {(float)(35.0/384.0), 0.f, (float)(500.0/1113.0), (float)(125.0/192.0),
   (float)(-2187.0/6784.0), (float)(11.0/84.0)}
};

// ---- packed f32x2 helpers (FFMA2 path for rhs) ----
__device__ __forceinline__ void ffma2(u64& d, u64 a, u64 b) {
  asm("fma.rn.f32x2 %0, %1, %2, %0;" : "+l"(d) : "l"(a), "l"(b));
}
__device__ __forceinline__ float2 unpack2(u64 v) {
  unsigned lo, hi;
  asm("mov.b64 {%0, %1}, %2;" : "=r"(lo), "=r"(hi) : "l"(v));
  return make_float2(__uint_as_float(lo), __uint_as_float(hi));
}

// Deterministic block-wide sum (fixed-shape tree); uniform across threads.
__device__ __forceinline__ float block_sum(float v, float* red) {
  __syncthreads();
  #pragma unroll
  for (int o = 16; o; o >>= 1) v += __shfl_down_sync(0xffffffffu, v, o);
  if ((threadIdx.x & 31) == 0) red[threadIdx.x >> 5] = v;
  __syncthreads();
  float s = ((red[0] + red[1]) + (red[2] + red[3]))
          + ((red[4] + red[5]) + (red[6] + red[7]));
  return s;
}

__device__ __forceinline__ unsigned ld_seq_cg(const unsigned* p) {
  unsigned v;
  asm volatile("ld.global.cg.u32 %0, [%1];" : "=r"(v) : "l"(p));
  return v;
}

// Fixed-shape 4-way tree over the 128 per-block partials (deterministic).
__device__ __forceinline__ float sum128_tree(const float* red2) {
  float p0 = 0.f, p1 = 0.f, p2 = 0.f, p3 = 0.f;
  #pragma unroll 8
  for (int i = 0; i < NBLK; i += 4) {
    p0 += red2[i];   p1 += red2[i+1];
    p2 += red2[i+2]; p3 += red2[i+3];
  }
  return (p0 + p1) + (p2 + p3);
}

// Release: payload __stcg -> __threadfence -> atomicExch(seq, rno).
__device__ __forceinline__ void gs_publish(float v, float* red, unsigned rno) {
  const int par = rno & 1;
  float b0 = block_sum(v, red);
  if (threadIdx.x == 0) {
    __stcg(&g_val[par][blockIdx.x], b0);
    __threadfence();
    atomicExch(&g_seq[blockIdx.x], rno);
  }
}
// Acquire: per-slot spin, fence, pull to SMEM, fixed-shape tree sum.
__device__ __forceinline__ float gs_gather(float* red, unsigned rno) {
  const int par = rno & 1;
  float* red2 = red + 8;
  const int b = threadIdx.x;
  if (b < NBLK) {
    while (ld_seq_cg(&g_seq[b]) < rno) __nanosleep(32);
    __threadfence();
    red2[b] = __ldcg(&g_val[par][b]);
  }
  __syncthreads();
  return sum128_tree(red2);
}

// Two-channel variant for init (publish+gather fused; doubles as grid barrier).
__device__ __forceinline__ void global_sum2(float v0, float v1, bool two,
                                            float* red, unsigned rno,
                                            float& s0, float& s1) {
  const int par = rno & 1;
  float b0 = block_sum(v0, red);
  float b1 = two ? block_sum(v1, red) : 0.f;
  float* red2 = red + 8;
  if (threadIdx.x == 0) {
    __stcg(&g_val[par][blockIdx.x], b0);
    if (two) __stcg(&g_val[par][NBLK + blockIdx.x], b1);
    __threadfence();
    atomicExch(&g_seq[blockIdx.x], rno);
  }
  const int b = threadIdx.x;
  if (b < NBLK) {
    while (ld_seq_cg(&g_seq[b]) < rno) __nanosleep(32);
    __threadfence();
    red2[b] = __ldcg(&g_val[par][b]);
    if (two) red2[NBLK + b] = __ldcg(&g_val[par][NBLK + b]);
  }
  __syncthreads();
  s0 = sum128_tree(red2);
  s1 = two ? sum128_tree(red2 + NBLK) : 0.f;
}

// RHS: k_u = -(v @ A^T), k_v = (u @ A^T). Thread owns 4 rows x 2 cols.
// kp 0..NKREG-1: A from registers. kp NKREG..15: A from parity-split SMEM.
// kp ascending; per-(row,col) even/odd-k FFMA2 order identical to rounds 3-13.
template<bool TOREG, bool TOSM>
__device__ __forceinline__ void rhs_eval(const float* __restrict__ y,
                                         float* __restrict__ kd,
                                         const float* __restrict__ Apk,
                                         const ulonglong2 (&ArE)[NKREG],
                                         const ulonglong2 (&ArO)[NKREG],
                                         int c0, int r0,
                                         float (&oU)[4][2], float (&oV)[4][2])
{
  const float* yu = y;
  const float* yv = y + ARR;
  const ulonglong2* __restrict__ AE2 = (const ulonglong2*)Apk;
  const ulonglong2* __restrict__ AO2 = (const ulonglong2*)(Apk + ARR);
  const int j = c0 >> 1;               // lane index 0..31
  u64 aU[4][2], aV[4][2];
  #pragma unroll
  for (int r = 0; r < 4; r++) {
    #pragma unroll
    for (int cc = 0; cc < 2; cc++) { aU[r][cc] = 0ull; aV[r][cc] = 0ull; }
  }
  // kp 0..NKREG-1: register-cached A
  #pragma unroll
  for (int kp = 0; kp < NKREG; kp++) {
    ulonglong2 A0 = ArE[kp];
    ulonglong2 A1 = ArO[kp];
    #pragma unroll
    for (int r = 0; r < 4; r++) {
      const int off = (r0 + r)*HID + kp*4;
      ulonglong2 v2 = *(const ulonglong2*)(yv + off);   // broadcast
      ulonglong2 u2 = *(const ulonglong2*)(yu + off);   // broadcast
      ffma2(aU[r][0], A0.x, v2.x); ffma2(aU[r][0], A0.y, v2.y);
      ffma2(aV[r][0], A0.x, u2.x); ffma2(aV[r][0], A0.y, u2.y);
      ffma2(aU[r][1], A1.x, v2.x); ffma2(aU[r][1], A1.y, v2.y);
      ffma2(aV[r][1], A1.x, u2.x); ffma2(aV[r][1], A1.y, u2.y);
    }
  }
  // kp NKREG..15: A from SMEM (conflict-free lane-contiguous)
  #pragma unroll 3
  for (int kp = NKREG; kp < 16; kp++) {
    ulonglong2 A0 = AE2[kp*32 + j];
    ulonglong2 A1 = AO2[kp*32 + j];
    #pragma unroll
    for (int r = 0; r < 4; r++) {
      const int off = (r0 + r)*HID + kp*4;
      ulonglong2 v2 = *(const ulonglong2*)(yv + off);   // broadcast
      ulonglong2 u2 = *(const ulonglong2*)(yu + off);   // broadcast
      ffma2(aU[r][0], A0.x, v2.x); ffma2(aU[r][0], A0.y, v2.y);
      ffma2(aV[r][0], A0.x, u2.x); ffma2(aV[r][0], A0.y, u2.y);
      ffma2(aU[r][1], A1.x, v2.x); ffma2(aU[r][1], A1.y, v2.y);
      ffma2(aV[r][1], A1.x, u2.x); ffma2(aV[r][1], A1.y, u2.y);
    }
  }
  #pragma unroll
  for (int r = 0; r < 4; r++) {
    float2 su0 = unpack2(aU[r][0]), su1 = unpack2(aU[r][1]);
    float2 sv0 = unpack2(aV[r][0]), sv1 = unpack2(aV[r][1]);
    float2 ku = make_float2(-(su0.x + su0.y), -(su1.x + su1.y));
    float2 kv = make_float2( (sv0.x + sv0.y),  (sv1.x + sv1.y));
    if (TOSM) {
      *(float2*)(kd + (r0+r)*HID + c0)       = ku;
      *(float2*)(kd + ARR + (r0+r)*HID + c0) = kv;
    }
    if (TOREG) {
      oU[r][0] = ku.x; oU[r][1] = ku.y;
      oV[r][0] = kv.x; oV[r][1] = kv.y;
    }
  }
}

__global__ void reset_kernel() {
  if (threadIdx.x < NBLK) g_seq[threadIdx.x] = 0u;
}

// Stage-state build helpers (identical per-element ops as rounds 10-13).
#define AXREG(B, KU, KV) { const float b_ = (B); \
  au.x = fmaf(b_, KU[r][0], au.x); au.y = fmaf(b_, KU[r][1], au.y); \
  av.x = fmaf(b_, KV[r][0], av.x); av.y = fmaf(b_, KV[r][1], av.y); }
#define AXSM(B, BASE) { const float b_ = (B); \
  float2 tu_ = *(const float2*)((BASE) + (r0+r)*HID + c0); \
  float2 tv_ = *(const float2*)((BASE) + ARR + (r0+r)*HID + c0); \
  au.x = fmaf(b_, tu_.x, au.x); au.y = fmaf(b_, tu_.y, au.y); \
  av.x = fmaf(b_, tv_.x, av.x); av.y = fmaf(b_, tv_.y, av.y); }
#define AXEND { float2 ou_, ov_; \
  ou_.x = fmaf(dt, au.x, yUr[r][0]); ou_.y = fmaf(dt, au.y, yUr[r][1]); \
  ov_.x = fmaf(dt, av.x, yVr[r][0]); ov_.y = fmaf(dt, av.y, yVr[r][1]); \
  *(float2*)(yalt + (r0+r)*HID + c0)       = ou_; \
  *(float2*)(yalt + ARR + (r0+r)*HID + c0) = ov_; }
#define AXBEGIN float2 au = make_float2(0.f,0.f), av = make_float2(0.f,0.f);

__global__ void __launch_bounds__(NTH, 1)
sindy_kernel(const float* __restrict__ x,
             const float* __restrict__ tri,
             float* __restrict__ out)
{
  extern __shared__ float sm[];
  const int tid  = threadIdx.x;
  const int c0   = (tid & 31) * 2;      // 2 adjacent columns
  const int r0   = (tid >> 5) * 4;      // warp owns 4 rows
  const int brow = blockIdx.x * RPB;

  float* Apk = sm + OFF_A;
  float* K   = sm + OFF_K;
  float* KS1 = K;
  float* KS2 = K + 1*YSZ;
  float* KS3 = K + 2*YSZ;
  float* KS4 = K + 3*YSZ;
  float* KS5 = K + 4*YSZ;
  float* Pb0 = sm + OFF_P;
  float* RED = sm + OFF_R;

  unsigned rno = 1;     // reduction round id (uniform across grid)
  int pp = 0;           // P parity (valid interp coefficients)

  // per-thread element registers (rows r0..r0+3, cols c0,c0+1)
  float yUr[4][2], yVr[4][2];
  float kU0[4][2], kV0[4][2];
  float kU6[4][2], kV6[4][2];
  ulonglong2 ArE[NKREG], ArO[NKREG];    // A cache, kp 0..NKREG-1

  const float CE0 = (float)(35.0/384.0 - 1951.0/21600.0);
  const float CE2 = (float)(500.0/1113.0 - 22642.0/50085.0);
  const float CE3 = (float)(125.0/192.0 - 451.0/720.0);
  const float CE4 = (float)(-2187.0/6784.0 + 12231.0/42400.0);
  const float CE5 = (float)(11.0/84.0 - 649.0/6300.0);
  const float CE6 = (float)(-1.0/60.0);
  const float CM0 = (float)(6025192743.0/30085553152.0/2.0);
  const float CM2 = (float)(51252292925.0/65400821598.0/2.0);
  const float CM3 = (float)(-2691868925.0/45128329728.0/2.0);
  const float CM4 = (float)(187940372067.0/1594534317056.0/2.0);
  const float CM5 = (float)(-1776094331.0/19743644256.0/2.0);
  const float CM6 = (float)(11237099.0/235043384.0/2.0);

  // Build parity-split kp-major A:
  //  AE[kp*128 + jj*4 + m] = A[2jj  ][kp*4+m]
  //  AO[kp*128 + jj*4 + m] = A[2jj+1][kp*4+m]
  for (int idx = tid; idx < HID*HID; idx += NTH) {
    int half = idx >> 11;
    int rem  = idx & 2047;
    int kp   = rem >> 7;
    int w    = rem & 127;
    int jj   = w >> 2, m = w & 3;
    int cc   = 2*jj + half;
    int k    = kp*4 + m;
    int R = cc > k ? cc : k, C = cc > k ? k : cc;
    Apk[half*ARR + kp*128 + jj*4 + m] = tri[R*(R+1)/2 + C];
  }

  // y0 = (x, 0); emit output slice t=1 (== y0 per odeint semantics)
  {
    float* Y0 = sm + OFF_Y;
    #pragma unroll
    for (int q = 0; q < 2; q++) {
      int e4 = tid + q*256;
      float4 xv = ((const float4*)x)[brow*16 + e4];
      ((float4*)Y0)[e4]         = xv;
      ((float4*)(Y0 + ARR))[e4] = make_float4(0.f, 0.f, 0.f, 0.f);
      int e = e4*4; int r = e >> 6; int h = e & 63;
      *(float4*)(out + ((size_t)(brow + r)*FORECAST + 0)*HID + h) = xv;
    }
  }
  __syncthreads();

  // load A cache (same bits as SMEM parity arrays)
  {
    const ulonglong2* AE2 = (const ulonglong2*)Apk;
    const ulonglong2* AO2 = (const ulonglong2*)(Apk + ARR);
    const int j = c0 >> 1;
    #pragma unroll
    for (int kp = 0; kp < NKREG; kp++) {
      ArE[kp] = AE2[kp*32 + j];
      ArO[kp] = AO2[kp*32 + j];
    }
  }

  int p = 0;
  float* ycur = sm + OFF_Y;
  float* yalt = sm + OFF_Y + YSZ;

  // f0 -> k0 regs (FSAL seed) + SMEM slot KS1 for init norms
  rhs_eval<true, true>(ycur, K, Apk, ArE, ArO, c0, r0, kU0, kV0);
  __syncthreads();

  // ---- initial_step_size (Hairer, order=4), GLOBAL norms ----
  float dt;
  {
    float s0 = 0.f, s1 = 0.f;
    #pragma unroll
    for (int q = 0; q < 4; q++) {
      int e4 = tid + q*256;
      float4 y4 = ((const float4*)ycur)[e4];
      float4 f4 = ((const float4*)K)[e4];
      float ys[4] = {y4.x, y4.y, y4.z, y4.w};
      float fs[4] = {f4.x, f4.y, f4.z, f4.w};
      #pragma unroll
      for (int m = 0; m < 4; m++) {
        float sc = 1e-3f + 1e-3f*fabsf(ys[m]);
        float a0 = ys[m]/sc, a1 = fs[m]/sc;
        s0 = fmaf(a0, a0, s0); s1 = fmaf(a1, a1, s1);
      }
    }
    float t0s, t1s;
    global_sum2(s0, s1, true, RED, rno, t0s, t1s); rno++;
    float d0 = sqrtf(t0s);
    float d1 = sqrtf(t1s);
    float h0 = (d0 < 1e-5f || d1 < 1e-5f) ? 1e-6f : 0.01f*d0/d1;
    #pragma unroll
    for (int q = 0; q < 4; q++) {
      int e4 = tid + q*256;
      float4 y4 = ((const float4*)ycur)[e4];
      float4 f4 = ((const float4*)K)[e4];
      float4 r4;
      r4.x = fmaf(h0, f4.x, y4.x); r4.y = fmaf(h0, f4.y, y4.y);
      r4.z = fmaf(h0, f4.z, y4.z); r4.w = fmaf(h0, f4.w, y4.w);
      ((float4*)yalt)[e4] = r4;
    }
    __syncthreads();
    rhs_eval<false, true>(yalt, K + YSZ, Apk, ArE, ArO, c0, r0, kU6, kV6);
    __syncthreads();
    float s2 = 0.f;
    #pragma unroll
    for (int q = 0; q < 4; q++) {
      int e4 = tid + q*256;
      float4 y4  = ((const float4*)ycur)[e4];
      float4 f0v = ((const float4*)K)[e4];
      float4 f1v = ((const float4*)(K + YSZ))[e4];
      float ys[4] = {y4.x, y4.y, y4.z, y4.w};
      float a0[4] = {f0v.x, f0v.y, f0v.z, f0v.w};
      float a1[4] = {f1v.x, f1v.y, f1v.z, f1v.w};
      #pragma unroll
      for (int m = 0; m < 4; m++) {
        float sc = 1e-3f + 1e-3f*fabsf(ys[m]);
        float d = (a1[m] - a0[m])/sc;
        s2 = fmaf(d, d, s2);
      }
    }
    float t2s, dum;
    global_sum2(s2, 0.f, false, RED, rno, t2s, dum); rno++;
    float d2 = sqrtf(t2s) / h0;
    float h1;
    if (d1 <= 1e-15f && d2 <= 1e-15f) h1 = fmaxf(1e-6f, h0*1e-3f);
    else                              h1 = powf(0.01f/fmaxf(d1, d2), 0.2f);
    dt = fminf(100.f*h0, h1);
  }

  // load thread-own y elements into registers
  #pragma unroll
  for (int r = 0; r < 4; r++) {
    float2 yu = *(const float2*)(ycur + (r0+r)*HID + c0);
    float2 yv = *(const float2*)(ycur + ARR + (r0+r)*HID + c0);
    yUr[r][0] = yu.x; yUr[r][1] = yu.y;
    yVr[r][0] = yv.x; yVr[r][1] = yv.y;
  }

  float t = 1.f, last_t = 1.f;

  // ---- main scan over output targets ----
  for (int tgt = 2; tgt <= FORECAST; tgt++) {
    float tf = (float)tgt;
    int guard = 0;
    while (t < tf && dt > 0.f && guard < 100000) {
      guard++;
      ycur = sm + OFF_Y + p*YSZ;
      yalt = sm + OFF_Y + (p^1)*YSZ;

      // ---- stages 1..6 (warp-local; k1..k5 in thread-own SMEM slots) ----
      // S1 -> k1
      #pragma unroll
      for (int r = 0; r < 4; r++) { AXBEGIN AXREG(BETAc[0][0], kU0, kV0) AXEND }
      __syncwarp();
      rhs_eval<false, true>(yalt, KS1, Apk, ArE, ArO, c0, r0, kU6, kV6);
      __syncwarp();
      // S2 -> k2
      #pragma unroll
      for (int r = 0; r < 4; r++) { AXBEGIN
        AXREG(BETAc[1][0], kU0, kV0) AXSM(BETAc[1][1], KS1) AXEND }
      __syncwarp();
      rhs_eval<false, true>(yalt, KS2, Apk, ArE, ArO, c0, r0, kU6, kV6);
      __syncwarp();
      // S3 -> k3
      #pragma unroll
      for (int r = 0; r < 4; r++) { AXBEGIN
        AXREG(BETAc[2][0], kU0, kV0) AXSM(BETAc[2][1], KS1)
        AXSM(BETAc[2][2], KS2) AXEND }
      __syncwarp();
      rhs_eval<false, true>(yalt, KS3, Apk, ArE, ArO, c0, r0, kU6, kV6);
      __syncwarp();
      // S4 -> k4
      #pragma unroll
      for (int r = 0; r < 4; r++) { AXBEGIN
        AXREG(BETAc[3][0], kU0, kV0) AXSM(BETAc[3][1], KS1)
        AXSM(BETAc[3][2], KS2) AXSM(BETAc[3][3], KS3) AXEND }
      __syncwarp();
      rhs_eval<false, true>(yalt, KS4, Apk, ArE, ArO, c0, r0, kU6, kV6);
      __syncwarp();
      // S5 -> k5
      #pragma unroll
      for (int r = 0; r < 4; r++) { AXBEGIN
        AXREG(BETAc[4][0], kU0, kV0) AXSM(BETAc[4][1], KS1)
        AXSM(BETAc[4][2], KS2) AXSM(BETAc[4][3], KS3)
        AXSM(BETAc[4][4], KS4) AXEND }
      __syncwarp();
      rhs_eval<false, true>(yalt, KS5, Apk, ArE, ArO, c0, r0, kU6, kV6);
      __syncwarp();
      // S6 -> k6 (regs); beta[5][1] == 0 -> k1 term skipped
      #pragma unroll
      for (int r = 0; r < 4; r++) { AXBEGIN
        AXREG(BETAc[5][0], kU0, kV0)
        AXSM(BETAc[5][2], KS2) AXSM(BETAc[5][3], KS3)
        AXSM(BETAc[5][4], KS4) AXSM(BETAc[5][5], KS5) AXEND }
      __syncwarp();
      rhs_eval<true, false>(yalt, K, Apk, ArE, ArO, c0, r0, kU6, kV6);
      __syncwarp();
      // yalt == y1 (FSAL)

      // ---- error-ratio partial (same value order as rounds 11-13) ----
      float ss = 0.f;
      #pragma unroll
      for (int r = 0; r < 4; r++) {
        float2 k2u = *(const float2*)(KS2 + (r0+r)*HID + c0);
        float2 k2v = *(const float2*)(KS2 + ARR + (r0+r)*HID + c0);
        float2 k3u = *(const float2*)(KS3 + (r0+r)*HID + c0);
        float2 k3v = *(const float2*)(KS3 + ARR + (r0+r)*HID + c0);
        float2 k4u = *(const float2*)(KS4 + (r0+r)*HID + c0);
        float2 k4v = *(const float2*)(KS4 + ARR + (r0+r)*HID + c0);
        float2 k5u = *(const float2*)(KS5 + (r0+r)*HID + c0);
        float2 k5v = *(const float2*)(KS5 + ARR + (r0+r)*HID + c0);
        float2 y1u = *(const float2*)(yalt + (r0+r)*HID + c0);
        float2 y1v = *(const float2*)(yalt + ARR + (r0+r)*HID + c0);
        #define EC(K0,K2,K3,K4,K5,K6,Y0,Y1) { \
          float er_ = dt*(CE0*(K0) + CE2*(K2) + CE3*(K3) + CE4*(K4) + CE5*(K5) + CE6*(K6)); \
          float tol_ = 1e-3f + 1e-3f*fmaxf(fabsf(Y0), fabsf(Y1)); \
          float rr_ = er_/tol_; ss = fmaf(rr_, rr_, ss); }
        EC(kU0[r][0],k2u.x,k3u.x,k4u.x,k5u.x,kU6[r][0],yUr[r][0],y1u.x)
        EC(kU0[r][1],k2u.y,k3u.y,k4u.y,k5u.y,kU6[r][1],yUr[r][1],y1u.y)
        EC(kV0[r][0],k2v.x,k3v.x,k4v.x,k5v.x,kV6[r][0],yVr[r][0],y1v.x)
        EC(kV0[r][1],k2v.y,k3v.y,k4v.y,k5v.y,kV6[r][1],yVr[r][1],y1v.y)
        #undef EC
      }
      gs_publish(ss, RED, rno);

      // ---- speculative interp coefficients (u only) into P[pp^1] ----
      {
        float* Pn = Pb0 + (pp^1)*PH;
        #pragma unroll
        for (int r = 0; r < 4; r++) {
          float2 k2u = *(const float2*)(KS2 + (r0+r)*HID + c0);
          float2 k3u = *(const float2*)(KS3 + (r0+r)*HID + c0);
          float2 k4u = *(const float2*)(KS4 + (r0+r)*HID + c0);
          float2 k5u = *(const float2*)(KS5 + (r0+r)*HID + c0);
          float2 y1u = *(const float2*)(yalt + (r0+r)*HID + c0);
          float2 A2f, B2f, C2f, D2f, E2f;
          #define IC(W, K0,K2,K3,K4,K5,K6,Y0,Y1) { \
            float ym = fmaf(dt, CM0*(K0) + CM2*(K2) + CM3*(K3) + CM4*(K4) + CM5*(K5) + CM6*(K6), (Y0)); \
            float D0 = dt*(K0), D1 = dt*(K6); \
            A2f.W = -2.f*D0 + 2.f*D1 -  8.f*(Y0) -  8.f*(Y1) + 16.f*ym; \
            B2f.W =  5.f*D0 - 3.f*D1 + 18.f*(Y0) + 14.f*(Y1) - 32.f*ym; \
            C2f.W = -4.f*D0 +     D1 - 11.f*(Y0) -  5.f*(Y1) + 16.f*ym; \
            D2f.W = D0; E2f.W = (Y0); }
          IC(x, kU0[r][0],k2u.x,k3u.x,k4u.x,k5u.x,kU6[r][0],yUr[r][0],y1u.x)
          IC(y, kU0[r][1],k2u.y,k3u.y,k4u.y,k5u.y,kU6[r][1],yUr[r][1],y1u.y)
          #undef IC
          const int obr = (r0+r)*HID + c0;
          *(float2*)(Pn + 0*ARR + obr) = A2f;
          *(float2*)(Pn + 1*ARR + obr) = B2f;
          *(float2*)(Pn + 2*ARR + obr) = C2f;
          *(float2*)(Pn + 3*ARR + obr) = D2f;
          *(float2*)(Pn + 4*ARR + obr) = E2f;
        }
      }

      float tss = gs_gather(RED, rno); rno++;
      float ratio  = sqrtf(tss * (1.f/524288.f));
      float er     = fmaxf(ratio, 1e-10f);
      float dfac   = (ratio < 1.f) ? 1.f : 0.2f;
      float factor = fminf(10.f, fmaxf(0.9f*powf(er, -0.2f), dfac));
      bool  accept = (ratio <= 1.f);

      if (accept) {
        pp ^= 1;                         // speculative P becomes valid
        // FSAL: k0 <- k6 (register copies)
        #pragma unroll
        for (int r = 0; r < 4; r++) {
          kU0[r][0] = kU6[r][0]; kU0[r][1] = kU6[r][1];
          kV0[r][0] = kV6[r][0]; kV0[r][1] = kV6[r][1];
        }
        // y-regs <- y1 (thread-own reload)
        #pragma unroll
        for (int r = 0; r < 4; r++) {
          float2 yu = *(const float2*)(yalt + (r0+r)*HID + c0);
          float2 yv = *(const float2*)(yalt + ARR + (r0+r)*HID + c0);
          yUr[r][0] = yu.x; yUr[r][1] = yu.y;
          yVr[r][0] = yv.x; yVr[r][1] = yv.y;
        }
        last_t = t; t = t + dt; p ^= 1;
      }
      // reject: k0/y regs intact; nothing to restore
      dt = dt * factor;
      __syncthreads();   // protect y buffers / P before next iteration
    }

    // evaluate interpolation polynomial at the target and store
    float xr = (tf - last_t) / (t - last_t);
    const float* Pc = Pb0 + pp*PH;
    #pragma unroll
    for (int q = 0; q < 2; q++) {
      int e4 = tid + q*256;
      float4 A4 = ((const float4*)Pc)[e4];
      float4 B4 = ((const float4*)(Pc +   ARR))[e4];
      float4 C4 = ((const float4*)(Pc + 2*ARR))[e4];
      float4 D4 = ((const float4*)(Pc + 3*ARR))[e4];
      float4 E4 = ((const float4*)(Pc + 4*ARR))[e4];
      float4 o;
      o.x = fmaf(fmaf(fmaf(fmaf(A4.x, xr, B4.x), xr, C4.x), xr, D4.x), xr, E4.x);
      o.y = fmaf(fmaf(fmaf(fmaf(A4.y, xr, B4.y), xr, C4.y), xr, D4.y), xr, E4.y);
      o.z = fmaf(fmaf(fmaf(fmaf(A4.z, xr, B4.z), xr, C4.z), xr, D4.z), xr, E4.z);
      o.w = fmaf(fmaf(fmaf(fmaf(A4.w, xr, B4.w), xr, C4.w), xr, D4.w), xr, E4.w);
      int e = e4*4; int r = e >> 6; int h = e & 63;
      *(float4*)(out + ((size_t)(brow + r)*FORECAST + (tgt - 1))*HID + h) = o;
    }
  }
}

extern "C" void kernel_launch(void* const* d_in, const int* in_sizes, int n_in,
                              void* d_out, int out_size) {
  (void)in_sizes; (void)n_in; (void)out_size;
  const float* x   = (const float*)d_in[0];
  const float* tri = (const float*)d_in[1];
  float* out = (float*)d_out;
  cudaFuncSetAttribute(sindy_kernel,
                       cudaFuncAttributeMaxDynamicSharedMemorySize, SMEM_BYTES);
  reset_kernel<<<1, 128>>>();
  sindy_kernel<<<NBLK, NTH, SMEM_BYTES>>>(x, tri, out);
}